// round 8
// baseline (speedup 1.0000x reference)
#include <cuda_runtime.h>
#include <math.h>

// POVMProjector: B=8, S=4096 -> R=32768 rows, IN_DIM=1024, OUT_DIM=256
// Inputs (dict order): d_in[0]=psi_re, d_in[1]=psi_im, d_in[2]=basis_re, d_in[3]=basis_im
// Output (float32, established by crash-boundary + beta/rho analysis):
//   d_out[0 .. R*1024)            = Re(collapsed_normalized)   (complex->float32 cast)
//   d_out[R*1024 .. R*1024+R*256) = probs

#define IN_DIM   1024
#define OUT_DIM  256
#define KC       16
#define MAX_R    32768
#define NCB      8          // number of 256-float column tiles in 2048

// Scratch (static device memory — allowed; no runtime allocation)
__device__ float g_coll[(size_t)MAX_R * 2048];   // unnormalized collapsed, interleaved re,im
__device__ float g_probs[MAX_R * OUT_DIM];
__device__ float g_nsq[MAX_R * NCB];
__device__ float g_scale[MAX_R];

// ---------------------------------------------------------------------------
// Kernel 1: inner = psi @ conj(basis)^H, p = |inner|^2, probs = p / (sum + eps)
// ---------------------------------------------------------------------------
__global__ __launch_bounds__(512, 1)
void probs_kernel(const float* __restrict__ pr, const float* __restrict__ pim,
                  const float* __restrict__ br, const float* __restrict__ bi,
                  float* __restrict__ probs_out)
{
    __shared__ float As_re[64][KC];
    __shared__ float As_im[64][KC];
    __shared__ float Bs_re[KC][OUT_DIM];
    __shared__ float Bs_im[KC][OUT_DIM];

    const int tx   = threadIdx.x;
    const int row0 = blockIdx.x * 64;
    const int wid  = tx >> 5;
    const int lane = tx & 31;

    float acc_re[4][8], acc_im[4][8];
#pragma unroll
    for (int r = 0; r < 4; r++)
#pragma unroll
        for (int c = 0; c < 8; c++) { acc_re[r][c] = 0.f; acc_im[r][c] = 0.f; }

    const int lrow = tx >> 3;
    const int lk   = (tx & 7) * 2;
    const int lm   = tx >> 1;
    const int lk2  = (tx & 1) * 8;

    const size_t prowOff = (size_t)(row0 + lrow) * IN_DIM + lk;
    const size_t browOff = (size_t)lm * IN_DIM + lk2;

    for (int k0 = 0; k0 < IN_DIM; k0 += KC) {
        __syncthreads();
        {
            float2 a0 = *(const float2*)(pr  + prowOff + k0);
            float2 a1 = *(const float2*)(pim + prowOff + k0);
            As_re[lrow][lk]     = a0.x;  As_re[lrow][lk + 1] = a0.y;
            As_im[lrow][lk]     = a1.x;  As_im[lrow][lk + 1] = a1.y;
        }
        {
            float4 b0 = *(const float4*)(br + browOff + k0);
            float4 b1 = *(const float4*)(br + browOff + k0 + 4);
            float4 c0 = *(const float4*)(bi + browOff + k0);
            float4 c1 = *(const float4*)(bi + browOff + k0 + 4);
            Bs_re[lk2 + 0][lm] = b0.x; Bs_re[lk2 + 1][lm] = b0.y;
            Bs_re[lk2 + 2][lm] = b0.z; Bs_re[lk2 + 3][lm] = b0.w;
            Bs_re[lk2 + 4][lm] = b1.x; Bs_re[lk2 + 5][lm] = b1.y;
            Bs_re[lk2 + 6][lm] = b1.z; Bs_re[lk2 + 7][lm] = b1.w;
            Bs_im[lk2 + 0][lm] = c0.x; Bs_im[lk2 + 1][lm] = c0.y;
            Bs_im[lk2 + 2][lm] = c0.z; Bs_im[lk2 + 3][lm] = c0.w;
            Bs_im[lk2 + 4][lm] = c1.x; Bs_im[lk2 + 5][lm] = c1.y;
            Bs_im[lk2 + 6][lm] = c1.z; Bs_im[lk2 + 7][lm] = c1.w;
        }
        __syncthreads();

#pragma unroll
        for (int kk = 0; kk < KC; kk++) {
            float ar[4], ai[4];
#pragma unroll
            for (int r = 0; r < 4; r++) {
                ar[r] = As_re[wid * 4 + r][kk];
                ai[r] = As_im[wid * 4 + r][kk];
            }
            float4 br0 = *(const float4*)&Bs_re[kk][lane * 4];
            float4 br1 = *(const float4*)&Bs_re[kk][128 + lane * 4];
            float4 bi0 = *(const float4*)&Bs_im[kk][lane * 4];
            float4 bi1 = *(const float4*)&Bs_im[kk][128 + lane * 4];
            float brv[8] = {br0.x, br0.y, br0.z, br0.w, br1.x, br1.y, br1.z, br1.w};
            float biv[8] = {bi0.x, bi0.y, bi0.z, bi0.w, bi1.x, bi1.y, bi1.z, bi1.w};
#pragma unroll
            for (int r = 0; r < 4; r++)
#pragma unroll
                for (int c = 0; c < 8; c++) {
                    acc_re[r][c] = fmaf(ar[r], brv[c], acc_re[r][c]);
                    acc_re[r][c] = fmaf(ai[r], biv[c], acc_re[r][c]);
                    acc_im[r][c] = fmaf(ai[r], brv[c], acc_im[r][c]);
                    acc_im[r][c] = fmaf(-ar[r], biv[c], acc_im[r][c]);
                }
        }
    }

    float p[4][8];
    float psum[4];
#pragma unroll
    for (int r = 0; r < 4; r++) {
        psum[r] = 0.f;
#pragma unroll
        for (int c = 0; c < 8; c++) {
            p[r][c] = acc_re[r][c] * acc_re[r][c] + acc_im[r][c] * acc_im[r][c];
            psum[r] += p[r][c];
        }
    }
#pragma unroll
    for (int off = 16; off > 0; off >>= 1) {
#pragma unroll
        for (int r = 0; r < 4; r++)
            psum[r] += __shfl_xor_sync(0xffffffffu, psum[r], off);
    }
#pragma unroll
    for (int r = 0; r < 4; r++) {
        const float inv = 1.f / (psum[r] + 1e-12f);
        const int row = row0 + wid * 4 + r;
        float4 o0 = make_float4(p[r][0] * inv, p[r][1] * inv, p[r][2] * inv, p[r][3] * inv);
        float4 o1 = make_float4(p[r][4] * inv, p[r][5] * inv, p[r][6] * inv, p[r][7] * inv);
        *(float4*)(probs_out + (size_t)row * OUT_DIM + lane * 4)       = o0;
        *(float4*)(probs_out + (size_t)row * OUT_DIM + 128 + lane * 4) = o1;
    }
}

// ---------------------------------------------------------------------------
// Kernel 2: collapsed_unnorm = probs @ basis -> g_coll (interleaved), + norm partials
// ---------------------------------------------------------------------------
__global__ __launch_bounds__(512, 1)
void collapse_kernel(const float* __restrict__ br, const float* __restrict__ bi,
                     const float* __restrict__ probs)
{
    __shared__ float Ps[64][KC];
    __shared__ float Bs[KC][256];

    const int tx   = threadIdx.x;
    const int row0 = blockIdx.x * 64;
    const int jb   = blockIdx.y * 256;
    const int wid  = tx >> 5;
    const int lane = tx & 31;

    float acc[4][8];
#pragma unroll
    for (int r = 0; r < 4; r++)
#pragma unroll
        for (int c = 0; c < 8; c++) acc[r][c] = 0.f;

    const int lrow = tx >> 3;
    const int lk   = (tx & 7) * 2;

    for (int k0 = 0; k0 < OUT_DIM; k0 += KC) {
        __syncthreads();
        {
            float2 pv = *(const float2*)(probs + (size_t)(row0 + lrow) * OUT_DIM + k0 + lk);
            Ps[lrow][lk]     = pv.x;
            Ps[lrow][lk + 1] = pv.y;
        }
        {
            const int m  = k0 + wid;
            const int i0 = (jb >> 1) + lane * 4;
            float4 re = *(const float4*)(br + (size_t)m * IN_DIM + i0);
            float4 im = *(const float4*)(bi + (size_t)m * IN_DIM + i0);
            float* d = &Bs[wid][lane * 8];
            *(float4*)(d)     = make_float4(re.x, im.x, re.y, im.y);
            *(float4*)(d + 4) = make_float4(re.z, im.z, re.w, im.w);
        }
        __syncthreads();

#pragma unroll
        for (int kk = 0; kk < KC; kk++) {
            float pv[4];
#pragma unroll
            for (int r = 0; r < 4; r++) pv[r] = Ps[wid * 4 + r][kk];
            float4 b0 = *(const float4*)&Bs[kk][lane * 4];
            float4 b1 = *(const float4*)&Bs[kk][128 + lane * 4];
            float bv[8] = {b0.x, b0.y, b0.z, b0.w, b1.x, b1.y, b1.z, b1.w};
#pragma unroll
            for (int r = 0; r < 4; r++)
#pragma unroll
                for (int c = 0; c < 8; c++)
                    acc[r][c] = fmaf(pv[r], bv[c], acc[r][c]);
        }
    }

    float s[4];
#pragma unroll
    for (int r = 0; r < 4; r++) {
        s[r] = 0.f;
#pragma unroll
        for (int c = 0; c < 8; c++) s[r] += acc[r][c] * acc[r][c];
    }
#pragma unroll
    for (int off = 16; off > 0; off >>= 1) {
#pragma unroll
        for (int r = 0; r < 4; r++)
            s[r] += __shfl_xor_sync(0xffffffffu, s[r], off);
    }
#pragma unroll
    for (int r = 0; r < 4; r++) {
        const int row = row0 + wid * 4 + r;
        if (lane == 0) g_nsq[row * NCB + blockIdx.y] = s[r];
        float4 o0 = make_float4(acc[r][0], acc[r][1], acc[r][2], acc[r][3]);
        float4 o1 = make_float4(acc[r][4], acc[r][5], acc[r][6], acc[r][7]);
        *(float4*)(g_coll + (size_t)row * 2048 + jb + lane * 4)       = o0;
        *(float4*)(g_coll + (size_t)row * 2048 + jb + 128 + lane * 4) = o1;
    }
}

// ---------------------------------------------------------------------------
// Kernel 3: per-row scale = 1 / (sqrt(full complex norm^2) + eps)
// ---------------------------------------------------------------------------
__global__ void norm_finalize_kernel(int R)
{
    int row = blockIdx.x * blockDim.x + threadIdx.x;
    if (row >= R) return;
    float s = 0.f;
#pragma unroll
    for (int j = 0; j < NCB; j++) s += g_nsq[row * NCB + j];
    g_scale[row] = 1.f / (sqrtf(s) + 1e-12f);
}

// ---------------------------------------------------------------------------
// Kernel 4: write Re(collapsed)*scale into d_out[0 .. R*1024), guarded.
// Each float4 out covers 4 complex cols -> reads 2 float4 from g_coll.
// ---------------------------------------------------------------------------
__global__ void scale_real_copy_kernel(float* __restrict__ dst, long long limit_floats, int n4)
{
    int i = blockIdx.x * blockDim.x + threadIdx.x;
    if (i >= n4) return;
    const int row  = i >> 8;                 // 256 float4 per 1024-float row
    const int cb   = (i & 255) * 2;          // float4 index pair base within row (of 512)
    const float sc = g_scale[row];
    const float4* src = (const float4*)g_coll + (size_t)row * 512 + cb;
    float4 a = src[0];
    float4 b = src[1];
    float4 o = make_float4(a.x * sc, a.z * sc, b.x * sc, b.z * sc);  // even elems = re
    const long long f0 = (long long)i * 4;
    if (f0 + 3 < limit_floats) {
        ((float4*)dst)[i] = o;
    } else {
        const float v[4] = {o.x, o.y, o.z, o.w};
        for (int j = 0; j < 4; j++)
            if (f0 + j < limit_floats) dst[f0 + j] = v[j];
    }
}

// ---------------------------------------------------------------------------
// Kernel 5: GUARDED copy of probs into d_out at float offset `off`.
// ---------------------------------------------------------------------------
__global__ void copy_probs_kernel(float* __restrict__ dst, long long off,
                                  long long limit_floats, int n4)
{
    int i = blockIdx.x * blockDim.x + threadIdx.x;
    if (i >= n4) return;
    const long long f0 = off + (long long)i * 4;
    if (f0 + 3 < limit_floats) {
        *(float4*)(dst + f0) = ((const float4*)g_probs)[i];
    } else {
        for (int j = 0; j < 4; j++)
            if (f0 + j < limit_floats)
                dst[f0 + j] = g_probs[(long long)i * 4 + j];
    }
}

// ---------------------------------------------------------------------------
extern "C" void kernel_launch(void* const* d_in, const int* in_sizes, int n_in,
                              void* d_out, int out_size)
{
    const float* pr  = (const float*)d_in[0];   // psi_re
    const float* pim = (const float*)d_in[1];   // psi_im
    const float* br  = (const float*)d_in[2];   // basis_re
    const float* bi  = (const float*)d_in[3];   // basis_im

    const int R = in_sizes[0] / IN_DIM;         // 32768
    float* out = (float*)d_out;

    float* probs_scratch;
    cudaGetSymbolAddress((void**)&probs_scratch, g_probs);

    probs_kernel<<<R / 64, 512>>>(pr, pim, br, bi, probs_scratch);
    collapse_kernel<<<dim3(R / 64, NCB), 512>>>(br, bi, probs_scratch);
    norm_finalize_kernel<<<(R + 255) / 256, 256>>>(R);

    const long long collR = (long long)R * IN_DIM;       // 33,554,432 (Re plane)
    const long long probF = (long long)R * OUT_DIM;      //  8,388,608
    const long long os    = (long long)out_size;

    // Output 0: Re(collapsed) at [0, collR), clamped to os.
    {
        const long long lim = (os < collR) ? os : collR;
        if (lim > 0) {
            const int n4 = (int)((lim + 3) / 4);
            scale_real_copy_kernel<<<(n4 + 255) / 256, 256>>>(out, lim, n4);
        }
    }
    // Output 1: probs at [collR, collR+probF), only if there is room beyond collR.
    if (os > collR) {
        const int p4 = (int)((probF + 3) / 4);
        copy_probs_kernel<<<(p4 + 255) / 256, 256>>>(out, collR, os, p4);
    }
}

// round 11
// speedup vs baseline: 1.8293x; 1.8293x over previous
#include <cuda_runtime.h>
#include <cuda_bf16.h>
#include <stdint.h>
#include <math.h>

// POVMProjector: R=32768 rows, IN_DIM=1024, OUT_DIM=256
// d_out = [ Re(collapsed) R*1024 | probs R*256 ]  (fp32) — confirmed R8.
// Split-bf16 (hi/lo) GEMMs via mma.sync (HMMA) — tcgen05 unavailable under compute_103.

#define R_TOT   32768
#define IN_DIM  1024
#define OUT_DIM 256

// ---------------- scratch (static device memory) ----------------
__device__ __nv_bfloat16 g_A1[(size_t)R_TOT * 4096];   // [pr_hi|pim_hi|pr_lo|pim_lo] per row
__device__ __nv_bfloat16 g_B1re[256 * 6144];           // [br_hi|bi_hi|br_hi|bi_hi|br_lo|bi_lo]
__device__ __nv_bfloat16 g_B1im[256 * 6144];           // [-bi_hi|br_hi|-bi_hi|br_hi|-bi_lo|br_lo]
__device__ float         g_ire[(size_t)R_TOT * 256];
__device__ float         g_iim[(size_t)R_TOT * 256];
__device__ __nv_bfloat16 g_A2[(size_t)R_TOT * 512];    // [p_hi|p_lo]
__device__ __nv_bfloat16 g_B2re[1024 * 768];           // [brT_hi|brT_hi|brT_lo]
__device__ __nv_bfloat16 g_B2im[1024 * 768];           // [biT_hi|biT_hi|biT_lo]
__device__ float         g_cre[(size_t)R_TOT * 1024];
__device__ float         g_cim[(size_t)R_TOT * 1024];

__device__ __forceinline__ uint32_t smem_u32(const void* p) {
    uint32_t a;
    asm("{ .reg .u64 t; cvta.to.shared.u64 t, %1; cvt.u32.u64 %0, t; }" : "=r"(a) : "l"(p));
    return a;
}
#define SWZ(o) ((o) ^ (((o) >> 3) & 0x70))

__device__ __forceinline__ void ldm_x4(uint32_t* r, uint32_t addr) {
    asm volatile("ldmatrix.sync.aligned.m8n8.x4.shared.b16 {%0,%1,%2,%3}, [%4];"
        : "=r"(r[0]), "=r"(r[1]), "=r"(r[2]), "=r"(r[3]) : "r"(addr));
}
__device__ __forceinline__ void mma_bf16(float* d, const uint32_t* a, const uint32_t* b) {
    asm volatile("mma.sync.aligned.m16n8k16.row.col.f32.bf16.bf16.f32 "
        "{%0,%1,%2,%3}, {%4,%5,%6,%7}, {%8,%9}, {%0,%1,%2,%3};"
        : "+f"(d[0]), "+f"(d[1]), "+f"(d[2]), "+f"(d[3])
        : "r"(a[0]), "r"(a[1]), "r"(a[2]), "r"(a[3]), "r"(b[0]), "r"(b[1]));
}

// ---------------------------------------------------------------------------
// Split-bf16 HMMA GEMM: C[M, ldc](plane) = A[M, lda-cat] x B[N, ldb-cat]^T
// CTA: 128x128, 256 thr (8 warps = 4M x 2N), warp tile 32x64, k-chunk 64.
// A chunk-wrap at `wrap` (A holds [hi|lo] only; B holds the full K-cat).
// ---------------------------------------------------------------------------
__global__ __launch_bounds__(256)
void mma_gemm(const __nv_bfloat16* __restrict__ A, int lda,
              const __nv_bfloat16* __restrict__ B0, const __nv_bfloat16* __restrict__ B1, int ldb,
              float* __restrict__ C0, float* __restrict__ C1, int ldc,
              int nchunks, int wrap)
{
    __shared__ __align__(1024) char smA[128 * 128];   // 128 rows x 64 bf16 (128B), SW128
    __shared__ __align__(1024) char smB[128 * 128];

    const int tid  = threadIdx.x;
    const int lane = tid & 31, warp = tid >> 5;
    const int wm   = warp >> 1, wn = warp & 1;
    const int row0 = blockIdx.x * 128;
    const int n0   = blockIdx.y * 128;
    const __nv_bfloat16* B = blockIdx.z ? B1 : B0;
    float* C = blockIdx.z ? C1 : C0;

    float acc[2][8][4];
#pragma unroll
    for (int mt = 0; mt < 2; mt++)
#pragma unroll
        for (int nt = 0; nt < 8; nt++)
#pragma unroll
            for (int j = 0; j < 4; j++) acc[mt][nt][j] = 0.f;

    // loader mapping: 2 threads per row, 32 bf16 (4 uint4) each
    const int lr = tid >> 1, lh = tid & 1;
    const __nv_bfloat16* gA = A + (size_t)(row0 + lr) * lda + lh * 32;
    const __nv_bfloat16* gB = B + (size_t)(n0 + lr) * ldb + lh * 32;
    uint32_t stoff[4];
#pragma unroll
    for (int j = 0; j < 4; j++) stoff[j] = SWZ((uint32_t)(lr * 128 + lh * 64 + j * 16));

    const uint32_t smA_u = smem_u32(smA), smB_u = smem_u32(smB);

    // precompute ldmatrix row bases
    uint32_t arow[2], brow[4];
#pragma unroll
    for (int mt = 0; mt < 2; mt++)
        arow[mt] = (uint32_t)((wm * 32 + mt * 16 + (lane & 15)) * 128 + (lane >> 4) * 16);
    {
        const int q = lane >> 3;
#pragma unroll
        for (int p = 0; p < 4; p++)
            brow[p] = (uint32_t)((wn * 64 + p * 16 + ((q & 2) ? 8 : 0) + (lane & 7)) * 128
                                 + (q & 1) * 16);
    }

    uint4 ra[4], rb[4];
    {
        const uint4* a4 = (const uint4*)gA;
        const uint4* b4 = (const uint4*)gB;
#pragma unroll
        for (int j = 0; j < 4; j++) { ra[j] = a4[j]; rb[j] = b4[j]; }
    }

    for (int ch = 0; ch < nchunks; ch++) {
        __syncthreads();
#pragma unroll
        for (int j = 0; j < 4; j++) {
            *(uint4*)(smA + stoff[j]) = ra[j];
            *(uint4*)(smB + stoff[j]) = rb[j];
        }
        __syncthreads();

        if (ch + 1 < nchunks) {
            const int ako = (((ch + 1) >= wrap) ? (ch + 1 - wrap) : (ch + 1)) * 64;
            const int bko = (ch + 1) * 64;
            const uint4* a4 = (const uint4*)(gA + ako);
            const uint4* b4 = (const uint4*)(gB + bko);
#pragma unroll
            for (int j = 0; j < 4; j++) { ra[j] = a4[j]; rb[j] = b4[j]; }
        }

#pragma unroll
        for (int ks = 0; ks < 4; ks++) {
            uint32_t afr[2][4];
#pragma unroll
            for (int mt = 0; mt < 2; mt++)
                ldm_x4(afr[mt], smA_u + SWZ(arow[mt] + (uint32_t)ks * 32));
            uint32_t bfr[8][2];
#pragma unroll
            for (int p = 0; p < 4; p++) {
                uint32_t r4[4];
                ldm_x4(r4, smB_u + SWZ(brow[p] + (uint32_t)ks * 32));
                bfr[2*p][0]   = r4[0]; bfr[2*p][1]   = r4[1];
                bfr[2*p+1][0] = r4[2]; bfr[2*p+1][1] = r4[3];
            }
#pragma unroll
            for (int mt = 0; mt < 2; mt++)
#pragma unroll
                for (int nt = 0; nt < 8; nt++)
                    mma_bf16(acc[mt][nt], afr[mt], bfr[nt]);
        }
    }

    // epilogue
    const int gid = lane >> 2, tig = lane & 3;
#pragma unroll
    for (int mt = 0; mt < 2; mt++) {
        const int rg = row0 + wm * 32 + mt * 16 + gid;
#pragma unroll
        for (int nt = 0; nt < 8; nt++) {
            const int cg = n0 + wn * 64 + nt * 8 + tig * 2;
            *(float2*)(C + (size_t)rg * ldc + cg)       = make_float2(acc[mt][nt][0], acc[mt][nt][1]);
            *(float2*)(C + (size_t)(rg + 8) * ldc + cg) = make_float2(acc[mt][nt][2], acc[mt][nt][3]);
        }
    }
}

// ---------------- conversion / epilogue kernels ----------------
__device__ __forceinline__ uint2 pack_hi4(float4 v) {
    __nv_bfloat162 a = __floats2bfloat162_rn(v.x, v.y);
    __nv_bfloat162 b = __floats2bfloat162_rn(v.z, v.w);
    uint2 r;
    r.x = *(uint32_t*)&a;
    r.y = *(uint32_t*)&b;
    return r;
}
__device__ __forceinline__ float4 resid4(float4 v, uint2 h) {
    __nv_bfloat162 a = *(__nv_bfloat162*)&h.x;
    __nv_bfloat162 b = *(__nv_bfloat162*)&h.y;
    return make_float4(v.x - __low2float(a), v.y - __high2float(a),
                       v.z - __low2float(b), v.w - __high2float(b));
}

__global__ void conv_psi(const float* __restrict__ pr, const float* __restrict__ pim)
{
    size_t i4 = (size_t)blockIdx.x * 256 + threadIdx.x;   // over R*1024/4
    float4 a = ((const float4*)pr)[i4];
    float4 b = ((const float4*)pim)[i4];
    size_t row = i4 >> 8;
    int    c   = (int)(i4 & 255) * 4;
    __nv_bfloat16* rp = g_A1 + row * 4096;
    uint2 ah = pack_hi4(a), bh = pack_hi4(b);
    uint2 al = pack_hi4(resid4(a, ah)), bl = pack_hi4(resid4(b, bh));
    *(uint2*)(rp + c)        = ah;
    *(uint2*)(rp + 1024 + c) = bh;
    *(uint2*)(rp + 2048 + c) = al;
    *(uint2*)(rp + 3072 + c) = bl;
}

__global__ void conv_basis1(const float* __restrict__ br, const float* __restrict__ bi)
{
    int idx = blockIdx.x * 256 + threadIdx.x;             // over 256*1024
    int m = idx >> 10, k = idx & 1023;
    float xr = br[idx], xi = bi[idx];
    __nv_bfloat16 rh = __float2bfloat16(xr);
    __nv_bfloat16 rl = __float2bfloat16(xr - __bfloat162float(rh));
    __nv_bfloat16 ih = __float2bfloat16(xi);
    __nv_bfloat16 il = __float2bfloat16(xi - __bfloat162float(ih));
    __nv_bfloat16 nih = __float2bfloat16(-xi);
    __nv_bfloat16 nil = __float2bfloat16(-xi - __bfloat162float(nih));
    size_t base = (size_t)m * 6144;
    g_B1re[base + k]        = rh;  g_B1re[base + 1024 + k] = ih;
    g_B1re[base + 2048 + k] = rh;  g_B1re[base + 3072 + k] = ih;
    g_B1re[base + 4096 + k] = rl;  g_B1re[base + 5120 + k] = il;
    g_B1im[base + k]        = nih; g_B1im[base + 1024 + k] = rh;
    g_B1im[base + 2048 + k] = nih; g_B1im[base + 3072 + k] = rh;
    g_B1im[base + 4096 + k] = nil; g_B1im[base + 5120 + k] = rl;
}

__global__ void conv_basis2(const float* __restrict__ br, const float* __restrict__ bi)
{
    int idx = blockIdx.x * 256 + threadIdx.x;             // over 1024*256
    int n = idx >> 8, m = idx & 255;
    float xr = br[(size_t)m * 1024 + n];
    float xi = bi[(size_t)m * 1024 + n];
    __nv_bfloat16 rh = __float2bfloat16(xr);
    __nv_bfloat16 rl = __float2bfloat16(xr - __bfloat162float(rh));
    __nv_bfloat16 ih = __float2bfloat16(xi);
    __nv_bfloat16 il = __float2bfloat16(xi - __bfloat162float(ih));
    size_t base = (size_t)n * 768;
    g_B2re[base + m] = rh;  g_B2re[base + 256 + m] = rh;  g_B2re[base + 512 + m] = rl;
    g_B2im[base + m] = ih;  g_B2im[base + 256 + m] = ih;  g_B2im[base + 512 + m] = il;
}

__global__ void probs_epi(float* __restrict__ dout)
{
    const int wid = threadIdx.x >> 5, lid = threadIdx.x & 31;
    const size_t row = (size_t)blockIdx.x * 8 + wid;
    const float4* re = (const float4*)(g_ire + row * 256);
    const float4* im = (const float4*)(g_iim + row * 256);
    float4 r0 = re[lid * 2], r1 = re[lid * 2 + 1];
    float4 i0 = im[lid * 2], i1 = im[lid * 2 + 1];
    float4 p0 = make_float4(r0.x*r0.x + i0.x*i0.x, r0.y*r0.y + i0.y*i0.y,
                            r0.z*r0.z + i0.z*i0.z, r0.w*r0.w + i0.w*i0.w);
    float4 p1 = make_float4(r1.x*r1.x + i1.x*i1.x, r1.y*r1.y + i1.y*i1.y,
                            r1.z*r1.z + i1.z*i1.z, r1.w*r1.w + i1.w*i1.w);
    float s = p0.x + p0.y + p0.z + p0.w + p1.x + p1.y + p1.z + p1.w;
#pragma unroll
    for (int off = 16; off > 0; off >>= 1) s += __shfl_xor_sync(0xffffffffu, s, off);
    const float inv = 1.f / (s + 1e-12f);
    float4 q0 = make_float4(p0.x*inv, p0.y*inv, p0.z*inv, p0.w*inv);
    float4 q1 = make_float4(p1.x*inv, p1.y*inv, p1.z*inv, p1.w*inv);
    float4* pdst = (float4*)(dout + (size_t)R_TOT * 1024 + row * 256);
    pdst[lid * 2]     = q0;
    pdst[lid * 2 + 1] = q1;
    uint2 h0 = pack_hi4(q0), h1 = pack_hi4(q1);
    uint2 l0 = pack_hi4(resid4(q0, h0)), l1 = pack_hi4(resid4(q1, h1));
    uint4 hv = make_uint4(h0.x, h0.y, h1.x, h1.y);
    uint4 lv = make_uint4(l0.x, l0.y, l1.x, l1.y);
    *(uint4*)(g_A2 + row * 512 + lid * 8)       = hv;
    *(uint4*)(g_A2 + row * 512 + 256 + lid * 8) = lv;
}

__global__ void norm_scale(float* __restrict__ dout)
{
    __shared__ float red[8];
    const size_t row = blockIdx.x;
    const int t = threadIdx.x, wid = t >> 5, lid = t & 31;
    float4 r  = ((const float4*)(g_cre + row * 1024))[t];
    float4 im = ((const float4*)(g_cim + row * 1024))[t];
    float s = r.x*r.x + r.y*r.y + r.z*r.z + r.w*r.w
            + im.x*im.x + im.y*im.y + im.z*im.z + im.w*im.w;
#pragma unroll
    for (int off = 16; off > 0; off >>= 1) s += __shfl_xor_sync(0xffffffffu, s, off);
    if (lid == 0) red[wid] = s;
    __syncthreads();
    float tot = red[0] + red[1] + red[2] + red[3] + red[4] + red[5] + red[6] + red[7];
    const float sc = 1.f / (sqrtf(tot) + 1e-12f);
    float4 o = make_float4(r.x * sc, r.y * sc, r.z * sc, r.w * sc);
    ((float4*)(dout + row * 1024))[t] = o;
}

// ---------------------------------------------------------------------------
extern "C" void kernel_launch(void* const* d_in, const int* in_sizes, int n_in,
                              void* d_out, int out_size)
{
    const float* pr  = (const float*)d_in[0];
    const float* pim = (const float*)d_in[1];
    const float* br  = (const float*)d_in[2];
    const float* bi  = (const float*)d_in[3];
    float* out = (float*)d_out;

    __nv_bfloat16 *a1, *b1re, *b1im, *a2, *b2re, *b2im;
    float *ire, *iim, *cre, *cim;
    cudaGetSymbolAddress((void**)&a1,   g_A1);
    cudaGetSymbolAddress((void**)&b1re, g_B1re);
    cudaGetSymbolAddress((void**)&b1im, g_B1im);
    cudaGetSymbolAddress((void**)&ire,  g_ire);
    cudaGetSymbolAddress((void**)&iim,  g_iim);
    cudaGetSymbolAddress((void**)&a2,   g_A2);
    cudaGetSymbolAddress((void**)&b2re, g_B2re);
    cudaGetSymbolAddress((void**)&b2im, g_B2im);
    cudaGetSymbolAddress((void**)&cre,  g_cre);
    cudaGetSymbolAddress((void**)&cim,  g_cim);

    // 1. conversions
    conv_psi<<<(R_TOT * IN_DIM / 4) / 256, 256>>>(pr, pim);
    conv_basis1<<<(256 * 1024) / 256, 256>>>(br, bi);
    conv_basis2<<<(1024 * 256) / 256, 256>>>(br, bi);

    // 2. GEMM1: inner = psi x conj(basis)^H  (M=32768, N=256, K=6144, wrap=64)
    mma_gemm<<<dim3(R_TOT / 128, 2, 2), 256>>>(a1, 4096, b1re, b1im, 6144,
                                               ire, iim, 256, 96, 64);

    // 3. probs + split for GEMM2
    probs_epi<<<R_TOT / 8, 256>>>(out);

    // 4. GEMM2: collapsed = probs x basis  (M=32768, N=1024/plane, K=768, wrap=8)
    mma_gemm<<<dim3(R_TOT / 128, 8, 2), 256>>>(a2, 512, b2re, b2im, 768,
                                               cre, cim, 1024, 12, 8);

    // 5. normalize + emit Re(collapsed)
    norm_scale<<<R_TOT, 256>>>(out);
}

// round 12
// speedup vs baseline: 2.4105x; 1.3177x over previous
#include <cuda_runtime.h>
#include <cuda_bf16.h>
#include <stdint.h>
#include <math.h>

// POVMProjector: R=32768 rows, IN_DIM=1024, OUT_DIM=256
// d_out = [ Re(collapsed) R*1024 | probs R*256 ]  (fp32) — confirmed R8.
// Split-bf16 (hi/lo) GEMMs via mma.sync HMMA + 3-stage cp.async pipeline.

#define R_TOT   32768
#define IN_DIM  1024
#define OUT_DIM 256

// ---------------- scratch (static device memory) ----------------
__device__ __nv_bfloat16 g_A1[(size_t)R_TOT * 4096];   // [pr_hi|pim_hi|pr_lo|pim_lo]
__device__ __nv_bfloat16 g_B1re[256 * 6144];           // [br_hi|bi_hi|br_hi|bi_hi|br_lo|bi_lo]
__device__ __nv_bfloat16 g_B1im[256 * 6144];           // [-bi_hi|br_hi|-bi_hi|br_hi|-bi_lo|br_lo]
__device__ float         g_ire[(size_t)R_TOT * 256];
__device__ float         g_iim[(size_t)R_TOT * 256];
__device__ __nv_bfloat16 g_A2[(size_t)R_TOT * 512];    // [p_hi|p_lo]
__device__ __nv_bfloat16 g_B2re[1024 * 768];           // [brT_hi|brT_hi|brT_lo]
__device__ __nv_bfloat16 g_B2im[1024 * 768];           // [biT_hi|biT_hi|biT_lo]
__device__ float         g_cre[(size_t)R_TOT * 1024];
__device__ float         g_cim[(size_t)R_TOT * 1024];

__device__ __forceinline__ uint32_t smem_u32(const void* p) {
    uint32_t a;
    asm("{ .reg .u64 t; cvta.to.shared.u64 t, %1; cvt.u32.u64 %0, t; }" : "=r"(a) : "l"(p));
    return a;
}
#define SWZ(o) ((o) ^ (((o) >> 3) & 0x70))

__device__ __forceinline__ void ldm_x4(uint32_t* r, uint32_t addr) {
    asm volatile("ldmatrix.sync.aligned.m8n8.x4.shared.b16 {%0,%1,%2,%3}, [%4];"
        : "=r"(r[0]), "=r"(r[1]), "=r"(r[2]), "=r"(r[3]) : "r"(addr));
}
__device__ __forceinline__ void mma_bf16(float* d, const uint32_t* a, const uint32_t* b) {
    asm volatile("mma.sync.aligned.m16n8k16.row.col.f32.bf16.bf16.f32 "
        "{%0,%1,%2,%3}, {%4,%5,%6,%7}, {%8,%9}, {%0,%1,%2,%3};"
        : "+f"(d[0]), "+f"(d[1]), "+f"(d[2]), "+f"(d[3])
        : "r"(a[0]), "r"(a[1]), "r"(a[2]), "r"(a[3]), "r"(b[0]), "r"(b[1]));
}
__device__ __forceinline__ void cp16(uint32_t dst, const void* src) {
    asm volatile("cp.async.cg.shared.global [%0], [%1], 16;" :: "r"(dst), "l"(src));
}
#define CP_COMMIT() asm volatile("cp.async.commit_group;" ::: "memory")
#define CP_WAIT(n)  asm volatile("cp.async.wait_group %0;" :: "n"(n) : "memory")

#define STAGE_BYTES 32768          // 16KB A + 16KB B per stage
#define NSTAGE      3
#define SM_TOTAL    (STAGE_BYTES * NSTAGE)   // 96 KB

// ---------------------------------------------------------------------------
// Split-bf16 HMMA GEMM, 3-stage cp.async pipeline.
// CTA: 128x128, 256 thr (8 warps = 4M x 2N), warp tile 32x64, k-chunk 64.
// A chunk-wrap at `wrap` (A holds [hi|lo] only; B holds the full K-cat).
// ---------------------------------------------------------------------------
__global__ __launch_bounds__(256, 2)
void mma_gemm(const __nv_bfloat16* __restrict__ A, int lda,
              const __nv_bfloat16* __restrict__ B0, const __nv_bfloat16* __restrict__ B1, int ldb,
              float* __restrict__ C0, float* __restrict__ C1, int ldc,
              int nchunks, int wrap)
{
    extern __shared__ __align__(1024) char smem[];

    const int tid  = threadIdx.x;
    const int lane = tid & 31, warp = tid >> 5;
    const int wm   = warp >> 1, wn = warp & 1;
    const int row0 = blockIdx.x * 128;
    const int n0   = blockIdx.y * 128;
    const __nv_bfloat16* B = blockIdx.z ? B1 : B0;
    float* C = blockIdx.z ? C1 : C0;

    float acc[2][8][4];
#pragma unroll
    for (int mt = 0; mt < 2; mt++)
#pragma unroll
        for (int nt = 0; nt < 8; nt++)
#pragma unroll
            for (int j = 0; j < 4; j++) acc[mt][nt][j] = 0.f;

    // loader mapping: 2 threads per row, 32 bf16 (4 x 16B) each
    const int lr = tid >> 1, lh = tid & 1;
    const __nv_bfloat16* gA = A + (size_t)(row0 + lr) * lda + lh * 32;
    const __nv_bfloat16* gB = B + (size_t)(n0 + lr) * ldb + lh * 32;
    uint32_t stoff[4];
#pragma unroll
    for (int j = 0; j < 4; j++) stoff[j] = SWZ((uint32_t)(lr * 128 + lh * 64 + j * 16));

    const uint32_t sm0 = smem_u32(smem);

    // ldmatrix row bases (within a 16KB tile)
    uint32_t arow[2], brow[4];
#pragma unroll
    for (int mt = 0; mt < 2; mt++)
        arow[mt] = (uint32_t)((wm * 32 + mt * 16 + (lane & 15)) * 128 + (lane >> 4) * 16);
    {
        const int q = lane >> 3;
#pragma unroll
        for (int p = 0; p < 4; p++)
            brow[p] = (uint32_t)((wn * 64 + p * 16 + ((q & 2) ? 8 : 0) + (lane & 7)) * 128
                                 + (q & 1) * 16);
    }

    // issue one chunk's loads into a stage
    auto issue = [&](int ch, int stage) {
        const int ako = ((ch >= wrap) ? ch - wrap : ch) * 64;
        const int bko = ch * 64;
        const char* asrc = (const char*)(gA + ako);
        const char* bsrc = (const char*)(gB + bko);
        const uint32_t ab = sm0 + stage * STAGE_BYTES;
        const uint32_t bb = ab + 16384;
#pragma unroll
        for (int j = 0; j < 4; j++) {
            cp16(ab + stoff[j], asrc + j * 16);
            cp16(bb + stoff[j], bsrc + j * 16);
        }
        CP_COMMIT();
    };

    // prologue: 2 chunks in flight
    issue(0, 0);
    if (nchunks > 1) issue(1, 1);

    int stage = 0;
    for (int ch = 0; ch < nchunks; ch++) {
        if (ch + 1 < nchunks) { CP_WAIT(1); } else { CP_WAIT(0); }
        __syncthreads();
        // refill the stage consumed 3 iterations ago (safe: barrier above)
        if (ch + 2 < nchunks) {
            int ns = stage + 2; if (ns >= NSTAGE) ns -= NSTAGE;
            issue(ch + 2, ns);
        }

        const uint32_t smA_u = sm0 + stage * STAGE_BYTES;
        const uint32_t smB_u = smA_u + 16384;
#pragma unroll
        for (int ks = 0; ks < 4; ks++) {
            uint32_t afr[2][4];
#pragma unroll
            for (int mt = 0; mt < 2; mt++)
                ldm_x4(afr[mt], smA_u + SWZ(arow[mt] + (uint32_t)ks * 32));
            uint32_t bfr[8][2];
#pragma unroll
            for (int p = 0; p < 4; p++) {
                uint32_t r4[4];
                ldm_x4(r4, smB_u + SWZ(brow[p] + (uint32_t)ks * 32));
                bfr[2*p][0]   = r4[0]; bfr[2*p][1]   = r4[1];
                bfr[2*p+1][0] = r4[2]; bfr[2*p+1][1] = r4[3];
            }
#pragma unroll
            for (int mt = 0; mt < 2; mt++)
#pragma unroll
                for (int nt = 0; nt < 8; nt++)
                    mma_bf16(acc[mt][nt], afr[mt], bfr[nt]);
        }
        stage++; if (stage >= NSTAGE) stage -= NSTAGE;
    }

    // epilogue
    const int gid = lane >> 2, tig = lane & 3;
#pragma unroll
    for (int mt = 0; mt < 2; mt++) {
        const int rg = row0 + wm * 32 + mt * 16 + gid;
#pragma unroll
        for (int nt = 0; nt < 8; nt++) {
            const int cg = n0 + wn * 64 + nt * 8 + tig * 2;
            *(float2*)(C + (size_t)rg * ldc + cg)       = make_float2(acc[mt][nt][0], acc[mt][nt][1]);
            *(float2*)(C + (size_t)(rg + 8) * ldc + cg) = make_float2(acc[mt][nt][2], acc[mt][nt][3]);
        }
    }
}

// ---------------- conversion / epilogue kernels ----------------
__device__ __forceinline__ uint2 pack_hi4(float4 v) {
    __nv_bfloat162 a = __floats2bfloat162_rn(v.x, v.y);
    __nv_bfloat162 b = __floats2bfloat162_rn(v.z, v.w);
    uint2 r;
    r.x = *(uint32_t*)&a;
    r.y = *(uint32_t*)&b;
    return r;
}
__device__ __forceinline__ float4 resid4(float4 v, uint2 h) {
    __nv_bfloat162 a = *(__nv_bfloat162*)&h.x;
    __nv_bfloat162 b = *(__nv_bfloat162*)&h.y;
    return make_float4(v.x - __low2float(a), v.y - __high2float(a),
                       v.z - __low2float(b), v.w - __high2float(b));
}

__global__ void conv_psi(const float* __restrict__ pr, const float* __restrict__ pim)
{
    size_t i4 = (size_t)blockIdx.x * 256 + threadIdx.x;
    float4 a = ((const float4*)pr)[i4];
    float4 b = ((const float4*)pim)[i4];
    size_t row = i4 >> 8;
    int    c   = (int)(i4 & 255) * 4;
    __nv_bfloat16* rp = g_A1 + row * 4096;
    uint2 ah = pack_hi4(a), bh = pack_hi4(b);
    uint2 al = pack_hi4(resid4(a, ah)), bl = pack_hi4(resid4(b, bh));
    *(uint2*)(rp + c)        = ah;
    *(uint2*)(rp + 1024 + c) = bh;
    *(uint2*)(rp + 2048 + c) = al;
    *(uint2*)(rp + 3072 + c) = bl;
}

__global__ void conv_basis1(const float* __restrict__ br, const float* __restrict__ bi)
{
    int idx = blockIdx.x * 256 + threadIdx.x;
    int m = idx >> 10, k = idx & 1023;
    float xr = br[idx], xi = bi[idx];
    __nv_bfloat16 rh = __float2bfloat16(xr);
    __nv_bfloat16 rl = __float2bfloat16(xr - __bfloat162float(rh));
    __nv_bfloat16 ih = __float2bfloat16(xi);
    __nv_bfloat16 il = __float2bfloat16(xi - __bfloat162float(ih));
    __nv_bfloat16 nih = __float2bfloat16(-xi);
    __nv_bfloat16 nil = __float2bfloat16(-xi - __bfloat162float(nih));
    size_t base = (size_t)m * 6144;
    g_B1re[base + k]        = rh;  g_B1re[base + 1024 + k] = ih;
    g_B1re[base + 2048 + k] = rh;  g_B1re[base + 3072 + k] = ih;
    g_B1re[base + 4096 + k] = rl;  g_B1re[base + 5120 + k] = il;
    g_B1im[base + k]        = nih; g_B1im[base + 1024 + k] = rh;
    g_B1im[base + 2048 + k] = nih; g_B1im[base + 3072 + k] = rh;
    g_B1im[base + 4096 + k] = nil; g_B1im[base + 5120 + k] = rl;
}

__global__ void conv_basis2(const float* __restrict__ br, const float* __restrict__ bi)
{
    int idx = blockIdx.x * 256 + threadIdx.x;
    int n = idx >> 8, m = idx & 255;
    float xr = br[(size_t)m * 1024 + n];
    float xi = bi[(size_t)m * 1024 + n];
    __nv_bfloat16 rh = __float2bfloat16(xr);
    __nv_bfloat16 rl = __float2bfloat16(xr - __bfloat162float(rh));
    __nv_bfloat16 ih = __float2bfloat16(xi);
    __nv_bfloat16 il = __float2bfloat16(xi - __bfloat162float(ih));
    size_t base = (size_t)n * 768;
    g_B2re[base + m] = rh;  g_B2re[base + 256 + m] = rh;  g_B2re[base + 512 + m] = rl;
    g_B2im[base + m] = ih;  g_B2im[base + 256 + m] = ih;  g_B2im[base + 512 + m] = il;
}

__global__ void probs_epi(float* __restrict__ dout)
{
    const int wid = threadIdx.x >> 5, lid = threadIdx.x & 31;
    const size_t row = (size_t)blockIdx.x * 8 + wid;
    const float4* re = (const float4*)(g_ire + row * 256);
    const float4* im = (const float4*)(g_iim + row * 256);
    float4 r0 = re[lid * 2], r1 = re[lid * 2 + 1];
    float4 i0 = im[lid * 2], i1 = im[lid * 2 + 1];
    float4 p0 = make_float4(r0.x*r0.x + i0.x*i0.x, r0.y*r0.y + i0.y*i0.y,
                            r0.z*r0.z + i0.z*i0.z, r0.w*r0.w + i0.w*i0.w);
    float4 p1 = make_float4(r1.x*r1.x + i1.x*i1.x, r1.y*r1.y + i1.y*i1.y,
                            r1.z*r1.z + i1.z*i1.z, r1.w*r1.w + i1.w*i1.w);
    float s = p0.x + p0.y + p0.z + p0.w + p1.x + p1.y + p1.z + p1.w;
#pragma unroll
    for (int off = 16; off > 0; off >>= 1) s += __shfl_xor_sync(0xffffffffu, s, off);
    const float inv = 1.f / (s + 1e-12f);
    float4 q0 = make_float4(p0.x*inv, p0.y*inv, p0.z*inv, p0.w*inv);
    float4 q1 = make_float4(p1.x*inv, p1.y*inv, p1.z*inv, p1.w*inv);
    float4* pdst = (float4*)(dout + (size_t)R_TOT * 1024 + row * 256);
    pdst[lid * 2]     = q0;
    pdst[lid * 2 + 1] = q1;
    uint2 h0 = pack_hi4(q0), h1 = pack_hi4(q1);
    uint2 l0 = pack_hi4(resid4(q0, h0)), l1 = pack_hi4(resid4(q1, h1));
    uint4 hv = make_uint4(h0.x, h0.y, h1.x, h1.y);
    uint4 lv = make_uint4(l0.x, l0.y, l1.x, l1.y);
    *(uint4*)(g_A2 + row * 512 + lid * 8)       = hv;
    *(uint4*)(g_A2 + row * 512 + 256 + lid * 8) = lv;
}

__global__ void norm_scale(float* __restrict__ dout)
{
    __shared__ float red[8];
    const size_t row = blockIdx.x;
    const int t = threadIdx.x, wid = t >> 5, lid = t & 31;
    float4 r  = ((const float4*)(g_cre + row * 1024))[t];
    float4 im = ((const float4*)(g_cim + row * 1024))[t];
    float s = r.x*r.x + r.y*r.y + r.z*r.z + r.w*r.w
            + im.x*im.x + im.y*im.y + im.z*im.z + im.w*im.w;
#pragma unroll
    for (int off = 16; off > 0; off >>= 1) s += __shfl_xor_sync(0xffffffffu, s, off);
    if (lid == 0) red[wid] = s;
    __syncthreads();
    float tot = red[0] + red[1] + red[2] + red[3] + red[4] + red[5] + red[6] + red[7];
    const float sc = 1.f / (sqrtf(tot) + 1e-12f);
    float4 o = make_float4(r.x * sc, r.y * sc, r.z * sc, r.w * sc);
    ((float4*)(dout + row * 1024))[t] = o;
}

// ---------------------------------------------------------------------------
extern "C" void kernel_launch(void* const* d_in, const int* in_sizes, int n_in,
                              void* d_out, int out_size)
{
    const float* pr  = (const float*)d_in[0];
    const float* pim = (const float*)d_in[1];
    const float* br  = (const float*)d_in[2];
    const float* bi  = (const float*)d_in[3];
    float* out = (float*)d_out;

    static int smem_set = 0;
    if (!smem_set) {
        cudaFuncSetAttribute(mma_gemm, cudaFuncAttributeMaxDynamicSharedMemorySize, SM_TOTAL);
        smem_set = 1;
    }

    __nv_bfloat16 *a1, *b1re, *b1im, *a2, *b2re, *b2im;
    float *ire, *iim, *cre, *cim;
    cudaGetSymbolAddress((void**)&a1,   g_A1);
    cudaGetSymbolAddress((void**)&b1re, g_B1re);
    cudaGetSymbolAddress((void**)&b1im, g_B1im);
    cudaGetSymbolAddress((void**)&ire,  g_ire);
    cudaGetSymbolAddress((void**)&iim,  g_iim);
    cudaGetSymbolAddress((void**)&a2,   g_A2);
    cudaGetSymbolAddress((void**)&b2re, g_B2re);
    cudaGetSymbolAddress((void**)&b2im, g_B2im);
    cudaGetSymbolAddress((void**)&cre,  g_cre);
    cudaGetSymbolAddress((void**)&cim,  g_cim);

    // 1. conversions
    conv_psi<<<(R_TOT * IN_DIM / 4) / 256, 256>>>(pr, pim);
    conv_basis1<<<(256 * 1024) / 256, 256>>>(br, bi);
    conv_basis2<<<(1024 * 256) / 256, 256>>>(br, bi);

    // 2. GEMM1: inner = psi x conj(basis)^H  (M=32768, N=256/plane, K=6144, wrap=64)
    mma_gemm<<<dim3(R_TOT / 128, 2, 2), 256, SM_TOTAL>>>(a1, 4096, b1re, b1im, 6144,
                                                         ire, iim, 256, 96, 64);

    // 3. probs + split for GEMM2
    probs_epi<<<R_TOT / 8, 256>>>(out);

    // 4. GEMM2: collapsed = probs x basis  (M=32768, N=1024/plane, K=768, wrap=8)
    mma_gemm<<<dim3(R_TOT / 128, 8, 2), 256, SM_TOTAL>>>(a2, 512, b2re, b2im, 768,
                                                         cre, cim, 1024, 12, 8);

    // 5. normalize + emit Re(collapsed)
    norm_scale<<<R_TOT, 256>>>(out);
}

// round 13
// speedup vs baseline: 2.5713x; 1.0667x over previous
#include <cuda_runtime.h>
#include <cuda_bf16.h>
#include <stdint.h>
#include <math.h>

// POVMProjector: R=32768 rows, IN_DIM=1024, OUT_DIM=256
// d_out = [ Re(collapsed) R*1024 | probs R*256 ]  (fp32) — confirmed R8.
// Split-bf16 HMMA + 3-stage cp.async + register-pipelined fragments.
// GEMM2 fused: im-plane never materialized; norm^2 partials from epilogue.

#define R_TOT   32768
#define IN_DIM  1024
#define OUT_DIM 256

// ---------------- scratch (static device memory) ----------------
__device__ __nv_bfloat16 g_A1[(size_t)R_TOT * 4096];   // [pr_hi|pim_hi|pr_lo|pim_lo]
__device__ __nv_bfloat16 g_B1re[256 * 6144];           // [br_hi|bi_hi|br_hi|bi_hi|br_lo|bi_lo]
__device__ __nv_bfloat16 g_B1im[256 * 6144];           // [-bi_hi|br_hi|-bi_hi|br_hi|-bi_lo|br_lo]
__device__ float         g_ire[(size_t)R_TOT * 256];
__device__ float         g_iim[(size_t)R_TOT * 256];
__device__ __nv_bfloat16 g_A2[(size_t)R_TOT * 512];    // [p_hi|p_lo]
__device__ __nv_bfloat16 g_B2re[1024 * 768];           // [brT_hi|brT_hi|brT_lo]
__device__ __nv_bfloat16 g_B2im[1024 * 768];           // [biT_hi|biT_hi|biT_lo]
__device__ float         g_cre[(size_t)R_TOT * 1024];
__device__ float         g_nsq[(size_t)R_TOT * 32];    // per-(row, yslice*2+wn, z) norm^2 partials

__device__ __forceinline__ uint32_t smem_u32(const void* p) {
    uint32_t a;
    asm("{ .reg .u64 t; cvta.to.shared.u64 t, %1; cvt.u32.u64 %0, t; }" : "=r"(a) : "l"(p));
    return a;
}
#define SWZ(o) ((o) ^ (((o) >> 3) & 0x70))

__device__ __forceinline__ void ldm_x4(uint32_t* r, uint32_t addr) {
    asm volatile("ldmatrix.sync.aligned.m8n8.x4.shared.b16 {%0,%1,%2,%3}, [%4];"
        : "=r"(r[0]), "=r"(r[1]), "=r"(r[2]), "=r"(r[3]) : "r"(addr));
}
__device__ __forceinline__ void mma_bf16(float* d, const uint32_t* a, const uint32_t* b) {
    asm volatile("mma.sync.aligned.m16n8k16.row.col.f32.bf16.bf16.f32 "
        "{%0,%1,%2,%3}, {%4,%5,%6,%7}, {%8,%9}, {%0,%1,%2,%3};"
        : "+f"(d[0]), "+f"(d[1]), "+f"(d[2]), "+f"(d[3])
        : "r"(a[0]), "r"(a[1]), "r"(a[2]), "r"(a[3]), "r"(b[0]), "r"(b[1]));
}
__device__ __forceinline__ void cp16(uint32_t dst, const void* src) {
    asm volatile("cp.async.cg.shared.global [%0], [%1], 16;" :: "r"(dst), "l"(src));
}
#define CP_COMMIT() asm volatile("cp.async.commit_group;" ::: "memory")
#define CP_WAIT(n)  asm volatile("cp.async.wait_group %0;" :: "n"(n) : "memory")

#define STAGE_BYTES 32768          // 16KB A + 16KB B per stage
#define NSTAGE      3
#define SM_TOTAL    (STAGE_BYTES * NSTAGE)   // 96 KB

// ---------------------------------------------------------------------------
// Split-bf16 HMMA GEMM, 3-stage cp.async + register double-buffered fragments.
// CTA: 128x128, 256 thr (8 warps = 4M x 2N), warp tile 32x64, k-chunk 64.
// If nsq != null: also emit per-(row, slice) sum of C^2 partials; if the
// plane's C pointer is null, skip the C store (norm-only plane).
// ---------------------------------------------------------------------------
__global__ __launch_bounds__(256)
void mma_gemm(const __nv_bfloat16* __restrict__ A, int lda,
              const __nv_bfloat16* __restrict__ B0, const __nv_bfloat16* __restrict__ B1, int ldb,
              float* __restrict__ C0, float* __restrict__ C1, int ldc,
              int nchunks, int wrap, float* __restrict__ nsq)
{
    extern __shared__ __align__(1024) char smem[];

    const int tid  = threadIdx.x;
    const int lane = tid & 31, warp = tid >> 5;
    const int wm   = warp >> 1, wn = warp & 1;
    const int row0 = blockIdx.x * 128;
    const int n0   = blockIdx.y * 128;
    float* C = blockIdx.z ? C1 : C0;
    const __nv_bfloat16* B = blockIdx.z ? B1 : B0;

    float acc[2][8][4];
#pragma unroll
    for (int mt = 0; mt < 2; mt++)
#pragma unroll
        for (int nt = 0; nt < 8; nt++)
#pragma unroll
            for (int j = 0; j < 4; j++) acc[mt][nt][j] = 0.f;

    // loader mapping: 2 threads per row, 32 bf16 (4 x 16B) each
    const int lr = tid >> 1, lh = tid & 1;
    const __nv_bfloat16* gA = A + (size_t)(row0 + lr) * lda + lh * 32;
    const __nv_bfloat16* gB = B + (size_t)(n0 + lr) * ldb + lh * 32;
    uint32_t stoff[4];
#pragma unroll
    for (int j = 0; j < 4; j++) stoff[j] = SWZ((uint32_t)(lr * 128 + lh * 64 + j * 16));

    const uint32_t sm0 = smem_u32(smem);

    // ldmatrix row bases (within a 16KB tile)
    uint32_t arow[2], brow[4];
#pragma unroll
    for (int mt = 0; mt < 2; mt++)
        arow[mt] = (uint32_t)((wm * 32 + mt * 16 + (lane & 15)) * 128 + (lane >> 4) * 16);
    {
        const int q = lane >> 3;
#pragma unroll
        for (int p = 0; p < 4; p++)
            brow[p] = (uint32_t)((wn * 64 + p * 16 + ((q & 2) ? 8 : 0) + (lane & 7)) * 128
                                 + (q & 1) * 16);
    }

    auto issue = [&](int ch, int stage) {
        const int ako = ((ch >= wrap) ? ch - wrap : ch) * 64;
        const int bko = ch * 64;
        const char* asrc = (const char*)(gA + ako);
        const char* bsrc = (const char*)(gB + bko);
        const uint32_t ab = sm0 + stage * STAGE_BYTES;
        const uint32_t bb = ab + 16384;
#pragma unroll
        for (int j = 0; j < 4; j++) {
            cp16(ab + stoff[j], asrc + j * 16);
            cp16(bb + stoff[j], bsrc + j * 16);
        }
        CP_COMMIT();
    };

    // double-buffered fragments
    uint32_t afr[2][2][4];
    uint32_t bfr[2][8][2];

    auto load_frags = [&](uint32_t smA_u, uint32_t smB_u, int ks, int buf) {
#pragma unroll
        for (int mt = 0; mt < 2; mt++)
            ldm_x4(afr[buf][mt], smA_u + SWZ(arow[mt] + (uint32_t)ks * 32));
#pragma unroll
        for (int p = 0; p < 4; p++) {
            uint32_t r4[4];
            ldm_x4(r4, smB_u + SWZ(brow[p] + (uint32_t)ks * 32));
            bfr[buf][2*p][0]   = r4[0]; bfr[buf][2*p][1]   = r4[1];
            bfr[buf][2*p+1][0] = r4[2]; bfr[buf][2*p+1][1] = r4[3];
        }
    };

    // prologue: 2 chunks in flight
    issue(0, 0);
    if (nchunks > 1) issue(1, 1);

    int stage = 0;
    for (int ch = 0; ch < nchunks; ch++) {
        if (ch + 1 < nchunks) { CP_WAIT(1); } else { CP_WAIT(0); }
        __syncthreads();

        const uint32_t smA_u = sm0 + stage * STAGE_BYTES;
        const uint32_t smB_u = smA_u + 16384;

        load_frags(smA_u, smB_u, 0, 0);          // start LDSM chain ASAP

        if (ch + 2 < nchunks) {                  // refill stage consumed 3 iters ago
            int ns = stage + 2; if (ns >= NSTAGE) ns -= NSTAGE;
            issue(ch + 2, ns);
        }

#pragma unroll
        for (int ks = 0; ks < 4; ks++) {
            const int cur = ks & 1;
            if (ks < 3) load_frags(smA_u, smB_u, ks + 1, cur ^ 1);
#pragma unroll
            for (int mt = 0; mt < 2; mt++)
#pragma unroll
                for (int nt = 0; nt < 8; nt++)
                    mma_bf16(acc[mt][nt], afr[cur][mt], bfr[cur][nt]);
        }
        stage++; if (stage >= NSTAGE) stage -= NSTAGE;
    }

    // epilogue
    const int gid = lane >> 2, tig = lane & 3;
#pragma unroll
    for (int mt = 0; mt < 2; mt++) {
        const int rg = row0 + wm * 32 + mt * 16 + gid;
        float s0 = 0.f, s1 = 0.f;
#pragma unroll
        for (int nt = 0; nt < 8; nt++) {
            const float a0 = acc[mt][nt][0], a1 = acc[mt][nt][1];
            const float a2 = acc[mt][nt][2], a3 = acc[mt][nt][3];
            if (nsq) { s0 += a0*a0 + a1*a1; s1 += a2*a2 + a3*a3; }
            if (C) {
                const int cg = n0 + wn * 64 + nt * 8 + tig * 2;
                *(float2*)(C + (size_t)rg * ldc + cg)       = make_float2(a0, a1);
                *(float2*)(C + (size_t)(rg + 8) * ldc + cg) = make_float2(a2, a3);
            }
        }
        if (nsq) {
            // reduce across the 4 tig lanes sharing each row
            s0 += __shfl_xor_sync(0xffffffffu, s0, 1);
            s0 += __shfl_xor_sync(0xffffffffu, s0, 2);
            s1 += __shfl_xor_sync(0xffffffffu, s1, 1);
            s1 += __shfl_xor_sync(0xffffffffu, s1, 2);
            if (tig == 0) {
                const int slot = (blockIdx.y * 2 + wn) * 2 + blockIdx.z;
                nsq[(size_t)rg * 32 + slot]       = s0;
                nsq[(size_t)(rg + 8) * 32 + slot] = s1;
            }
        }
    }
}

// ---------------- conversion / epilogue kernels ----------------
__device__ __forceinline__ uint2 pack_hi4(float4 v) {
    __nv_bfloat162 a = __floats2bfloat162_rn(v.x, v.y);
    __nv_bfloat162 b = __floats2bfloat162_rn(v.z, v.w);
    uint2 r;
    r.x = *(uint32_t*)&a;
    r.y = *(uint32_t*)&b;
    return r;
}
__device__ __forceinline__ float4 resid4(float4 v, uint2 h) {
    __nv_bfloat162 a = *(__nv_bfloat162*)&h.x;
    __nv_bfloat162 b = *(__nv_bfloat162*)&h.y;
    return make_float4(v.x - __low2float(a), v.y - __high2float(a),
                       v.z - __low2float(b), v.w - __high2float(b));
}

__global__ void conv_psi(const float* __restrict__ pr, const float* __restrict__ pim)
{
    size_t i4 = (size_t)blockIdx.x * 256 + threadIdx.x;
    float4 a = ((const float4*)pr)[i4];
    float4 b = ((const float4*)pim)[i4];
    size_t row = i4 >> 8;
    int    c   = (int)(i4 & 255) * 4;
    __nv_bfloat16* rp = g_A1 + row * 4096;
    uint2 ah = pack_hi4(a), bh = pack_hi4(b);
    uint2 al = pack_hi4(resid4(a, ah)), bl = pack_hi4(resid4(b, bh));
    *(uint2*)(rp + c)        = ah;
    *(uint2*)(rp + 1024 + c) = bh;
    *(uint2*)(rp + 2048 + c) = al;
    *(uint2*)(rp + 3072 + c) = bl;
}

__global__ void conv_basis1(const float* __restrict__ br, const float* __restrict__ bi)
{
    int idx = blockIdx.x * 256 + threadIdx.x;
    int m = idx >> 10, k = idx & 1023;
    float xr = br[idx], xi = bi[idx];
    __nv_bfloat16 rh = __float2bfloat16(xr);
    __nv_bfloat16 rl = __float2bfloat16(xr - __bfloat162float(rh));
    __nv_bfloat16 ih = __float2bfloat16(xi);
    __nv_bfloat16 il = __float2bfloat16(xi - __bfloat162float(ih));
    __nv_bfloat16 nih = __float2bfloat16(-xi);
    __nv_bfloat16 nil = __float2bfloat16(-xi - __bfloat162float(nih));
    size_t base = (size_t)m * 6144;
    g_B1re[base + k]        = rh;  g_B1re[base + 1024 + k] = ih;
    g_B1re[base + 2048 + k] = rh;  g_B1re[base + 3072 + k] = ih;
    g_B1re[base + 4096 + k] = rl;  g_B1re[base + 5120 + k] = il;
    g_B1im[base + k]        = nih; g_B1im[base + 1024 + k] = rh;
    g_B1im[base + 2048 + k] = nih; g_B1im[base + 3072 + k] = rh;
    g_B1im[base + 4096 + k] = nil; g_B1im[base + 5120 + k] = rl;
}

__global__ void conv_basis2(const float* __restrict__ br, const float* __restrict__ bi)
{
    int idx = blockIdx.x * 256 + threadIdx.x;
    int n = idx >> 8, m = idx & 255;
    float xr = br[(size_t)m * 1024 + n];
    float xi = bi[(size_t)m * 1024 + n];
    __nv_bfloat16 rh = __float2bfloat16(xr);
    __nv_bfloat16 rl = __float2bfloat16(xr - __bfloat162float(rh));
    __nv_bfloat16 ih = __float2bfloat16(xi);
    __nv_bfloat16 il = __float2bfloat16(xi - __bfloat162float(ih));
    size_t base = (size_t)n * 768;
    g_B2re[base + m] = rh;  g_B2re[base + 256 + m] = rh;  g_B2re[base + 512 + m] = rl;
    g_B2im[base + m] = ih;  g_B2im[base + 256 + m] = ih;  g_B2im[base + 512 + m] = il;
}

__global__ void probs_epi(float* __restrict__ dout)
{
    const int wid = threadIdx.x >> 5, lid = threadIdx.x & 31;
    const size_t row = (size_t)blockIdx.x * 8 + wid;
    const float4* re = (const float4*)(g_ire + row * 256);
    const float4* im = (const float4*)(g_iim + row * 256);
    float4 r0 = re[lid * 2], r1 = re[lid * 2 + 1];
    float4 i0 = im[lid * 2], i1 = im[lid * 2 + 1];
    float4 p0 = make_float4(r0.x*r0.x + i0.x*i0.x, r0.y*r0.y + i0.y*i0.y,
                            r0.z*r0.z + i0.z*i0.z, r0.w*r0.w + i0.w*i0.w);
    float4 p1 = make_float4(r1.x*r1.x + i1.x*i1.x, r1.y*r1.y + i1.y*i1.y,
                            r1.z*r1.z + i1.z*i1.z, r1.w*r1.w + i1.w*i1.w);
    float s = p0.x + p0.y + p0.z + p0.w + p1.x + p1.y + p1.z + p1.w;
#pragma unroll
    for (int off = 16; off > 0; off >>= 1) s += __shfl_xor_sync(0xffffffffu, s, off);
    const float inv = 1.f / (s + 1e-12f);
    float4 q0 = make_float4(p0.x*inv, p0.y*inv, p0.z*inv, p0.w*inv);
    float4 q1 = make_float4(p1.x*inv, p1.y*inv, p1.z*inv, p1.w*inv);
    float4* pdst = (float4*)(dout + (size_t)R_TOT * 1024 + row * 256);
    pdst[lid * 2]     = q0;
    pdst[lid * 2 + 1] = q1;
    uint2 h0 = pack_hi4(q0), h1 = pack_hi4(q1);
    uint2 l0 = pack_hi4(resid4(q0, h0)), l1 = pack_hi4(resid4(q1, h1));
    uint4 hv = make_uint4(h0.x, h0.y, h1.x, h1.y);
    uint4 lv = make_uint4(l0.x, l0.y, l1.x, l1.y);
    *(uint4*)(g_A2 + row * 512 + lid * 8)       = hv;
    *(uint4*)(g_A2 + row * 512 + 256 + lid * 8) = lv;
}

// final: scale = 1/(sqrt(sum of 32 partials)+eps); out = cre*scale
__global__ void norm_scale(float* __restrict__ dout)
{
    const size_t row = blockIdx.x;
    const int t = threadIdx.x, lid = t & 31;
    float p = g_nsq[row * 32 + lid];
#pragma unroll
    for (int off = 16; off > 0; off >>= 1) p += __shfl_xor_sync(0xffffffffu, p, off);
    const float sc = 1.f / (sqrtf(p) + 1e-12f);
    float4 r = ((const float4*)(g_cre + row * 1024))[t];
    ((float4*)(dout + row * 1024))[t] =
        make_float4(r.x * sc, r.y * sc, r.z * sc, r.w * sc);
}

// ---------------------------------------------------------------------------
extern "C" void kernel_launch(void* const* d_in, const int* in_sizes, int n_in,
                              void* d_out, int out_size)
{
    const float* pr  = (const float*)d_in[0];
    const float* pim = (const float*)d_in[1];
    const float* br  = (const float*)d_in[2];
    const float* bi  = (const float*)d_in[3];
    float* out = (float*)d_out;

    static int smem_set = 0;
    if (!smem_set) {
        cudaFuncSetAttribute(mma_gemm, cudaFuncAttributeMaxDynamicSharedMemorySize, SM_TOTAL);
        smem_set = 1;
    }

    __nv_bfloat16 *a1, *b1re, *b1im, *a2, *b2re, *b2im;
    float *ire, *iim, *cre, *nsq;
    cudaGetSymbolAddress((void**)&a1,   g_A1);
    cudaGetSymbolAddress((void**)&b1re, g_B1re);
    cudaGetSymbolAddress((void**)&b1im, g_B1im);
    cudaGetSymbolAddress((void**)&ire,  g_ire);
    cudaGetSymbolAddress((void**)&iim,  g_iim);
    cudaGetSymbolAddress((void**)&a2,   g_A2);
    cudaGetSymbolAddress((void**)&b2re, g_B2re);
    cudaGetSymbolAddress((void**)&b2im, g_B2im);
    cudaGetSymbolAddress((void**)&cre,  g_cre);
    cudaGetSymbolAddress((void**)&nsq,  g_nsq);

    // 1. conversions
    conv_psi<<<(R_TOT * IN_DIM / 4) / 256, 256>>>(pr, pim);
    conv_basis1<<<(256 * 1024) / 256, 256>>>(br, bi);
    conv_basis2<<<(1024 * 256) / 256, 256>>>(br, bi);

    // 2. GEMM1: inner = psi x conj(basis)^H  (M=32768, N=256/plane, K=6144, wrap=64)
    mma_gemm<<<dim3(R_TOT / 128, 2, 2), 256, SM_TOTAL>>>(a1, 4096, b1re, b1im, 6144,
                                                         ire, iim, 256, 96, 64, nullptr);

    // 3. probs + split for GEMM2
    probs_epi<<<R_TOT / 8, 256>>>(out);

    // 4. GEMM2: collapsed = probs x basis (M=32768, N=1024/plane, K=768, wrap=8)
    //    re-plane -> g_cre; im-plane -> norm partials only (no C store).
    mma_gemm<<<dim3(R_TOT / 128, 8, 2), 256, SM_TOTAL>>>(a2, 512, b2re, b2im, 768,
                                                         cre, nullptr, 1024, 12, 8, nsq);

    // 5. normalize + emit Re(collapsed)
    norm_scale<<<R_TOT, 256>>>(out);
}